// round 3
// baseline (speedup 1.0000x reference)
#include <cuda_runtime.h>

// SupConLoss on GB300 (sm_103a).
// features: [4096, 2, 128] fp32 ; labels: [4096] (int32 or int64 — detected) ; out: scalar fp32.
//
//   cf[v*B+b]  = features[b,v,:] normalized, scaled by 1/sqrt(T)  (dot == logit)
//   phase 1:   s[j]  = sum_i [lab_i != lab_j] * exp(l_ij)
//   phase 2:   total = sum_{i,j} [lab_i == lab_j, i != j] * (l_ij - log(s_j + e^l_ij))
//   out = -total / N
// Symmetry: logits/masks symmetric -> compute only tiles I <= J; off-diagonal
// tiles contribute both their own and the mirrored terms.

#define BATCH 4096
#define NN    8192
#define TILE  64
#define INV_SQRT_T 3.7796447300922722f   // 1/sqrt(0.07)

__device__ float g_cfh[NN * 128];  // normalized+scaled vectors (4 MB, L2-resident)
__device__ int   g_lab[NN];
__device__ float g_s[NN];
__device__ int   g_is64;           // 1 if labels buffer is int64, 0 if int32

// ---------------------------------------------------------------------------
// packed f32x2 helpers (sm_103a FFMA2; only reachable via PTX)
// ---------------------------------------------------------------------------
__device__ __forceinline__ unsigned long long packf2(float lo, float hi) {
    unsigned long long r;
    asm("mov.b64 %0, {%1, %2};" : "=l"(r) : "f"(lo), "f"(hi));
    return r;
}
__device__ __forceinline__ void unpackf2(float &lo, float &hi, unsigned long long v) {
    asm("mov.b64 {%0, %1}, %2;" : "=f"(lo), "=f"(hi) : "l"(v));
}
#define FMA2(acc, a, b) \
    asm("fma.rn.f32x2 %0, %1, %2, %0;" : "+l"(acc) : "l"(a), "l"(b))

// ---------------------------------------------------------------------------
// detect label dtype. Labels are in [0,100). If the buffer is int64 (little-
// endian), every odd 32-bit word (high half) is 0. If int32, odd words are
// labels[1],labels[3],... — all zero with prob ~0.99^2048 ~ 1e-9.
// ---------------------------------------------------------------------------
__global__ void k_detect(const int* __restrict__ lab32) {
    __shared__ int s_any[256];
    int v = 0;
    for (int i = threadIdx.x; i < BATCH / 2; i += 256) v |= lab32[2 * i + 1];
    s_any[threadIdx.x] = v;
    __syncthreads();
    for (int o = 128; o; o >>= 1) {
        if (threadIdx.x < o) s_any[threadIdx.x] |= s_any[threadIdx.x + o];
        __syncthreads();
    }
    if (threadIdx.x == 0) g_is64 = (s_any[0] == 0) ? 1 : 0;
}

// ---------------------------------------------------------------------------
// prep: normalize rows, fold 1/sqrt(T), expand labels, zero accumulators.
// One warp per row. grid = NN/8 x 256.
// ---------------------------------------------------------------------------
__global__ void k_prep(const float* __restrict__ feat,
                       const int* __restrict__ lab32,
                       float* __restrict__ out, int out_size) {
    int t    = threadIdx.x;
    int warp = t >> 5, lane = t & 31;
    int n    = blockIdx.x * 8 + warp;           // cf row, 0..8191

    if (blockIdx.x == 0) {
        for (int z = t; z < out_size; z += 256) out[z] = 0.0f;
    }
    if (lane == 0) g_s[n] = 0.0f;

    // cf[v*B + b] = features[b, v, :]
    int v = n >> 12;
    int b = n & (BATCH - 1);
    const float4* f4 = reinterpret_cast<const float4*>(feat) +
                       (size_t)(b * 2 + v) * 32;
    float4 x = f4[lane];

    float ss = x.x * x.x + x.y * x.y + x.z * x.z + x.w * x.w;
#pragma unroll
    for (int o = 16; o; o >>= 1) ss += __shfl_xor_sync(0xffffffffu, ss, o);

    float sc = rsqrtf(ss) * INV_SQRT_T;
    float4 y = make_float4(x.x * sc, x.y * sc, x.z * sc, x.w * sc);
    reinterpret_cast<float4*>(g_cfh)[(size_t)n * 32 + lane] = y;

    if (lane == 0) {
        // int64 layout: low word of element b is at word index 2b; int32: b.
        g_lab[n] = g_is64 ? lab32[2 * b] : lab32[b];
    }
}

// ---------------------------------------------------------------------------
// phase kernel: 64x64 logit tile per block; only tiles with I <= J do work.
// 256 threads, 16x16 grid, 4x4 micro-tile each, packed FFMA2 core.
// ---------------------------------------------------------------------------
template <int PHASE>
__global__ void __launch_bounds__(256, 4) k_phase(float* __restrict__ out) {
    const int I = blockIdx.y, J = blockIdx.x;
    if (J < I) return;

    __shared__ __align__(16) float As[64 * 64];  // As[k][i_local]
    __shared__ __align__(16) float Bs[64 * 64];  // Bs[k][j_local]
    __shared__ float redc[16 * 64];
    __shared__ float redr[16 * 64];
    __shared__ int   labA[64], labB[64];
    __shared__ float sA[64], sB[64];

    const int t  = threadIdx.x;
    const int i0 = I * TILE, j0 = J * TILE;

    if (t < 64) {
        labA[t] = g_lab[i0 + t];
        if (PHASE == 2) sA[t] = g_s[i0 + t];
    } else if (t < 128) {
        int u = t - 64;
        labB[u] = g_lab[j0 + u];
        if (PHASE == 2) sB[u] = g_s[j0 + u];
    }

    unsigned long long acc[4][2];
#pragma unroll
    for (int r = 0; r < 4; ++r) { acc[r][0] = 0ull; acc[r][1] = 0ull; }

    const float4* cf4 = reinterpret_cast<const float4*>(g_cfh);
    const int ty = t >> 4, tx = t & 15;
    const int lrow = t & 63;
    const int lsub = t >> 6;   // 0..3

    for (int kc = 0; kc < 2; ++kc) {
        __syncthreads();
        // load + transpose this 64-wide K chunk: gmem [row][k] -> smem [k][row]
#pragma unroll
        for (int ch = 0; ch < 4; ++ch) {
            int k4 = ch * 4 + lsub;                    // float4-k, 0..15
            float4 a  = cf4[(size_t)(i0 + lrow) * 32 + kc * 16 + k4];
            float4 bq = cf4[(size_t)(j0 + lrow) * 32 + kc * 16 + k4];
            int k = k4 * 4;
            As[(k + 0) * 64 + lrow] = a.x;
            As[(k + 1) * 64 + lrow] = a.y;
            As[(k + 2) * 64 + lrow] = a.z;
            As[(k + 3) * 64 + lrow] = a.w;
            Bs[(k + 0) * 64 + lrow] = bq.x;
            Bs[(k + 1) * 64 + lrow] = bq.y;
            Bs[(k + 2) * 64 + lrow] = bq.z;
            Bs[(k + 3) * 64 + lrow] = bq.w;
        }
        __syncthreads();

        const float4* As4 = reinterpret_cast<const float4*>(As);
        const float4* Bs4 = reinterpret_cast<const float4*>(Bs);
#pragma unroll 4
        for (int k = 0; k < 64; ++k) {
            float4 a = As4[k * 16 + ty];
            float4 b = Bs4[k * 16 + tx];
            unsigned long long b01 = packf2(b.x, b.y);
            unsigned long long b23 = packf2(b.z, b.w);
            unsigned long long a0 = packf2(a.x, a.x);
            unsigned long long a1 = packf2(a.y, a.y);
            unsigned long long a2 = packf2(a.z, a.z);
            unsigned long long a3 = packf2(a.w, a.w);
            FMA2(acc[0][0], a0, b01); FMA2(acc[0][1], a0, b23);
            FMA2(acc[1][0], a1, b01); FMA2(acc[1][1], a1, b23);
            FMA2(acc[2][0], a2, b01); FMA2(acc[2][1], a2, b23);
            FMA2(acc[3][0], a3, b01); FMA2(acc[3][1], a3, b23);
        }
    }

    // logits: row i0 + ty*4 + r, col j0 + tx*4 + c
    float accf[4][4];
#pragma unroll
    for (int r = 0; r < 4; ++r) {
        unpackf2(accf[r][0], accf[r][1], acc[r][0]);
        unpackf2(accf[r][2], accf[r][3], acc[r][1]);
    }

    int li[4], lj[4];
#pragma unroll
    for (int r = 0; r < 4; ++r) li[r] = labA[ty * 4 + r];
#pragma unroll
    for (int c = 0; c < 4; ++c) lj[c] = labB[tx * 4 + c];

    if (PHASE == 1) {
        // s[j] += col sums; for I<J the mirrored entries give s[i] += row sums
        float colp[4] = {0.f, 0.f, 0.f, 0.f};
        float rowp[4] = {0.f, 0.f, 0.f, 0.f};
#pragma unroll
        for (int r = 0; r < 4; ++r)
#pragma unroll
            for (int c = 0; c < 4; ++c) {
                float e = __expf(accf[r][c]);
                if (li[r] != lj[c]) { colp[c] += e; rowp[r] += e; }
            }
#pragma unroll
        for (int c = 0; c < 4; ++c) redc[ty * 64 + tx * 4 + c] = colp[c];
#pragma unroll
        for (int r = 0; r < 4; ++r) redr[tx * 64 + ty * 4 + r] = rowp[r];
        __syncthreads();
        if (t < 64) {
            float s1 = 0.f;
#pragma unroll
            for (int m = 0; m < 16; ++m) s1 += redc[m * 64 + t];
            atomicAdd(&g_s[j0 + t], s1);
            if (I != J) {
                float s2 = 0.f;
#pragma unroll
                for (int m = 0; m < 16; ++m) s2 += redr[m * 64 + t];
                atomicAdd(&g_s[i0 + t], s2);
            }
        }
    } else {
        // total += pos*(l - log(s_j + e)); off-diag tiles add the mirrored term
        float local = 0.f;
#pragma unroll
        for (int r = 0; r < 4; ++r)
#pragma unroll
            for (int c = 0; c < 4; ++c) {
                if (li[r] == lj[c]) {
                    float l = accf[r][c];
                    if (I == J) {
                        if (ty * 4 + r != tx * 4 + c) {
                            float e = __expf(l);
                            local += l - __logf(sB[tx * 4 + c] + e);
                        }
                    } else {
                        float e = __expf(l);
                        local += 2.0f * l - __logf(sB[tx * 4 + c] + e)
                                          - __logf(sA[ty * 4 + r] + e);
                    }
                }
            }
#pragma unroll
        for (int o = 16; o; o >>= 1)
            local += __shfl_xor_sync(0xffffffffu, local, o);
        if ((t & 31) == 0) redc[t >> 5] = local;
        __syncthreads();
        if (t == 0) {
            float s = 0.f;
#pragma unroll
            for (int w = 0; w < 8; ++w) s += redc[w];
            atomicAdd(out, s * (-1.0f / (float)NN));
        }
    }
}

// ---------------------------------------------------------------------------
extern "C" void kernel_launch(void* const* d_in, const int* in_sizes, int n_in,
                              void* d_out, int out_size) {
    const float* feat  = (const float*)d_in[0];
    const int*   lab32 = (const int*)d_in[1];
    float*       out   = (float*)d_out;

    k_detect<<<1, 256>>>(lab32);
    k_prep<<<NN / 8, 256>>>(feat, lab32, out, out_size);

    dim3 grid(NN / TILE, NN / TILE);   // lower-triangle blocks exit immediately
    k_phase<1><<<grid, 256>>>(out);
    k_phase<2><<<grid, 256>>>(out);
}

// round 4
// speedup vs baseline: 2.3811x; 2.3811x over previous
#include <cuda_runtime.h>

// SupConLoss on GB300 (sm_103a).
// features: [4096,2,128] fp32 ; labels: [4096] (int32/int64 auto-detect) ; out: scalar fp32.
//
//   cf[v*B+b] = features[b,v,:] normalized * 1/sqrt(T)   (dot == logit)
//   ONE GEMM pass over upper-triangular 128x128 tiles:
//     s[j] += sum_i [lab_i != lab_j] exp(l_ij)   (+ mirrored row sums for I<J)
//     positives (gi<gj) appended to a global list (i,j,l)
//   finalize: total = sum_list (2l - log(s_j+e^l) - log(s_i+e^l));  out = -total/N

#define BATCH 4096
#define NN    8192
#define BT    128                       // block tile
#define INV_SQRT_T 3.7796447300922722f  // 1/sqrt(0.07)
#define LCAP  (8 * 1024 * 1024)

__device__ float g_cfh[NN * 128];   // normalized vectors (4 MB, L2-resident)
__device__ int   g_lab[NN];
__device__ float g_s[NN];
__device__ int   g_is64;
__device__ int   g_cnt;
__device__ unsigned g_lp[LCAP];     // packed (i<<13)|j
__device__ float    g_lv[LCAP];     // logit

// ---------------- packed f32x2 helpers (sm_103a FFMA2 via PTX) --------------
__device__ __forceinline__ unsigned long long packf2(float lo, float hi) {
    unsigned long long r;
    asm("mov.b64 %0, {%1, %2};" : "=l"(r) : "f"(lo), "f"(hi));
    return r;
}
__device__ __forceinline__ void unpackf2(float &lo, float &hi, unsigned long long v) {
    asm("mov.b64 {%0, %1}, %2;" : "=f"(lo), "=f"(hi) : "l"(v));
}
#define FMA2(acc, a, b) \
    asm("fma.rn.f32x2 %0, %1, %2, %0;" : "+l"(acc) : "l"(a), "l"(b))

// ---------------- label dtype detect (int64 high words are all zero) --------
__global__ void k_detect(const int* __restrict__ lab32) {
    __shared__ int s_any[256];
    int v = 0;
    for (int i = threadIdx.x; i < BATCH / 2; i += 256) v |= lab32[2 * i + 1];
    s_any[threadIdx.x] = v;
    __syncthreads();
    for (int o = 128; o; o >>= 1) {
        if (threadIdx.x < o) s_any[threadIdx.x] |= s_any[threadIdx.x + o];
        __syncthreads();
    }
    if (threadIdx.x == 0) g_is64 = (s_any[0] == 0) ? 1 : 0;
}

// ---------------- prep: normalize + scale, labels, zero accumulators -------
__global__ void k_prep(const float* __restrict__ feat,
                       const int* __restrict__ lab32,
                       float* __restrict__ out, int out_size) {
    int t = threadIdx.x, warp = t >> 5, lane = t & 31;
    int n = blockIdx.x * 8 + warp;

    if (blockIdx.x == 0) {
        for (int z = t; z < out_size; z += 256) out[z] = 0.0f;
        if (t == 0) g_cnt = 0;
    }
    if (lane == 0) g_s[n] = 0.0f;

    int v = n >> 12, b = n & (BATCH - 1);
    const float4* f4 = reinterpret_cast<const float4*>(feat) + (size_t)(b * 2 + v) * 32;
    float4 x = f4[lane];
    float ss = x.x * x.x + x.y * x.y + x.z * x.z + x.w * x.w;
#pragma unroll
    for (int o = 16; o; o >>= 1) ss += __shfl_xor_sync(0xffffffffu, ss, o);
    float sc = rsqrtf(ss) * INV_SQRT_T;
    reinterpret_cast<float4*>(g_cfh)[(size_t)n * 32 + lane] =
        make_float4(x.x * sc, x.y * sc, x.z * sc, x.w * sc);
    if (lane == 0) g_lab[n] = g_is64 ? lab32[2 * b] : lab32[b];
}

// ---------------- main: 128x128 tile GEMM + fused epilogue ------------------
// 256 threads (16x16), 8x8 micro-tile, rows {ty*4..+3, 64+ty*4..+3},
// cols {tx*4..+3, 64+tx*4..+3} (interleaved for 2-phase LDS). K chunks of 32.
__global__ void __launch_bounds__(256, 2) k_main() {
    const int I = blockIdx.y, J = blockIdx.x;
    if (J < I) return;

    __shared__ __align__(16) float As[32 * 128];  // As[k][row]
    __shared__ __align__(16) float Bs[32 * 128];  // Bs[k][col]
    __shared__ float redc[16 * 128];
    __shared__ float redr[16 * 128];
    __shared__ int   labA[128], labB[128];
    __shared__ int   s_warp[8], s_base;

    const int t  = threadIdx.x;
    const int i0 = I * BT, j0 = J * BT;
    const int ty = t >> 4, tx = t & 15;

    if (t < 128) labA[t] = g_lab[i0 + t];
    else         labB[t - 128] = g_lab[j0 + (t - 128)];

    unsigned long long acc[8][4];
#pragma unroll
    for (int r = 0; r < 8; ++r)
#pragma unroll
        for (int c = 0; c < 4; ++c) acc[r][c] = 0ull;

    const float4* cf4 = reinterpret_cast<const float4*>(g_cfh);
    const int lrow = t & 127;
    const int half = t >> 7;           // 0/1 : which 4 float4s of the row

    for (int kc = 0; kc < 4; ++kc) {
        __syncthreads();
        // load K-chunk [rows][32k] transposed into smem [k][row]
#pragma unroll
        for (int ch = 0; ch < 4; ++ch) {
            int k4 = half * 4 + ch;                       // float4-k 0..7
            float4 a  = cf4[(size_t)(i0 + lrow) * 32 + kc * 8 + k4];
            float4 bq = cf4[(size_t)(j0 + lrow) * 32 + kc * 8 + k4];
            int k = k4 * 4;
            As[(k + 0) * 128 + lrow] = a.x;  As[(k + 1) * 128 + lrow] = a.y;
            As[(k + 2) * 128 + lrow] = a.z;  As[(k + 3) * 128 + lrow] = a.w;
            Bs[(k + 0) * 128 + lrow] = bq.x; Bs[(k + 1) * 128 + lrow] = bq.y;
            Bs[(k + 2) * 128 + lrow] = bq.z; Bs[(k + 3) * 128 + lrow] = bq.w;
        }
        __syncthreads();

        const float4* As4 = reinterpret_cast<const float4*>(As);
        const float4* Bs4 = reinterpret_cast<const float4*>(Bs);
#pragma unroll 4
        for (int k = 0; k < 32; ++k) {
            float4 a0 = As4[k * 32 + ty];        // rows ty*4..+3
            float4 a1 = As4[k * 32 + 16 + ty];   // rows 64+ty*4..+3
            float4 b0 = Bs4[k * 32 + tx];        // cols tx*4..+3
            float4 b1 = Bs4[k * 32 + 16 + tx];   // cols 64+tx*4..+3
            unsigned long long bp[4] = { packf2(b0.x, b0.y), packf2(b0.z, b0.w),
                                         packf2(b1.x, b1.y), packf2(b1.z, b1.w) };
            float av[8] = { a0.x, a0.y, a0.z, a0.w, a1.x, a1.y, a1.z, a1.w };
#pragma unroll
            for (int r = 0; r < 8; ++r) {
                unsigned long long ap = packf2(av[r], av[r]);
                FMA2(acc[r][0], ap, bp[0]); FMA2(acc[r][1], ap, bp[1]);
                FMA2(acc[r][2], ap, bp[2]); FMA2(acc[r][3], ap, bp[3]);
            }
        }
    }

    // unpack: accf[r][c], r/c index 0..7 with global offset rule below
    float accf[8][8];
#pragma unroll
    for (int r = 0; r < 8; ++r) {
        unpackf2(accf[r][0], accf[r][1], acc[r][0]);
        unpackf2(accf[r][2], accf[r][3], acc[r][1]);
        unpackf2(accf[r][4], accf[r][5], acc[r][2]);
        unpackf2(accf[r][6], accf[r][7], acc[r][3]);
    }
    int rl[8], cl[8], li[8], lj[8];
#pragma unroll
    for (int r = 0; r < 8; ++r) {
        rl[r] = (r < 4) ? ty * 4 + r : 64 + ty * 4 + (r - 4);
        cl[r] = (r < 4) ? tx * 4 + r : 64 + tx * 4 + (r - 4);
    }
#pragma unroll
    for (int r = 0; r < 8; ++r) { li[r] = labA[rl[r]]; lj[r] = labB[cl[r]]; }

    // --- neg-masked exp sums ---
    float colp[8] = {0,0,0,0,0,0,0,0}, rowp[8] = {0,0,0,0,0,0,0,0};
    int n_pos = 0;
#pragma unroll
    for (int r = 0; r < 8; ++r)
#pragma unroll
        for (int c = 0; c < 8; ++c) {
            float e = __expf(accf[r][c]);
            if (li[r] != lj[c]) { colp[c] += e; rowp[r] += e; }
            else if (I != J || rl[r] < cl[c]) ++n_pos;
        }
#pragma unroll
    for (int c = 0; c < 8; ++c) redc[ty * 128 + cl[c]] = colp[c];
#pragma unroll
    for (int r = 0; r < 8; ++r) redr[tx * 128 + rl[r]] = rowp[r];
    __syncthreads();
    if (t < 128) {
        float s1 = 0.f;
#pragma unroll
        for (int m = 0; m < 16; ++m) s1 += redc[m * 128 + t];
        atomicAdd(&g_s[j0 + t], s1);
        if (I != J) {
            float s2 = 0.f;
#pragma unroll
            for (int m = 0; m < 16; ++m) s2 += redr[m * 128 + t];
            atomicAdd(&g_s[i0 + t], s2);
        }
    }

    // --- append positives: block-aggregated reservation, then write ---
    int lane = t & 31, wid = t >> 5;
    int x = n_pos;
#pragma unroll
    for (int o = 1; o < 32; o <<= 1) {
        int y = __shfl_up_sync(0xffffffffu, x, o);
        if (lane >= o) x += y;
    }
    if (lane == 31) s_warp[wid] = x;      // warp totals
    __syncthreads();
    if (t == 0) {
        int s = 0;
#pragma unroll
        for (int w = 0; w < 8; ++w) { int v = s_warp[w]; s_warp[w] = s; s += v; }
        s_base = s ? atomicAdd(&g_cnt, s) : 0;
    }
    __syncthreads();
    int slot = s_base + s_warp[wid] + (x - n_pos);
#pragma unroll
    for (int r = 0; r < 8; ++r)
#pragma unroll
        for (int c = 0; c < 8; ++c) {
            if (li[r] == lj[c] && (I != J || rl[r] < cl[c])) {
                if (slot < LCAP) {
                    g_lp[slot] = ((unsigned)(i0 + rl[r]) << 13) | (unsigned)(j0 + cl[c]);
                    g_lv[slot] = accf[r][c];
                }
                ++slot;
            }
        }
}

// ---------------- finalize: loss over the positive list --------------------
__global__ void k_final(float* __restrict__ out) {
    __shared__ float red[8];
    int cnt = g_cnt; if (cnt > LCAP) cnt = LCAP;
    int idx = blockIdx.x * 256 + threadIdx.x;
    int stride = gridDim.x * 256;
    float local = 0.f;
    for (int k = idx; k < cnt; k += stride) {
        unsigned p = g_lp[k];
        int i = p >> 13, j = p & 8191;
        float l = g_lv[k];
        float e = __expf(l);
        local += 2.0f * l - __logf(g_s[j] + e) - __logf(g_s[i] + e);
    }
#pragma unroll
    for (int o = 16; o; o >>= 1) local += __shfl_xor_sync(0xffffffffu, local, o);
    if ((threadIdx.x & 31) == 0) red[threadIdx.x >> 5] = local;
    __syncthreads();
    if (threadIdx.x == 0) {
        float s = 0.f;
#pragma unroll
        for (int w = 0; w < 8; ++w) s += red[w];
        if (s != 0.0f) atomicAdd(out, s * (-1.0f / (float)NN));
    }
}

// ---------------------------------------------------------------------------
extern "C" void kernel_launch(void* const* d_in, const int* in_sizes, int n_in,
                              void* d_out, int out_size) {
    const float* feat  = (const float*)d_in[0];
    const int*   lab32 = (const int*)d_in[1];
    float*       out   = (float*)d_out;

    k_detect<<<1, 256>>>(lab32);
    k_prep<<<NN / 8, 256>>>(feat, lab32, out, out_size);
    dim3 grid(NN / BT, NN / BT);          // lower-triangle blocks exit
    k_main<<<grid, 256>>>();
    k_final<<<512, 256>>>(out);
}

// round 6
// speedup vs baseline: 4.4319x; 1.8612x over previous
#include <cuda_runtime.h>
#include <cuda_bf16.h>
#include <cstdint>

// SupConLoss on GB300 (sm_103a harness, ptxas target sm_103 => legacy tensor
// cores via mma.sync bf16; tcgen05 unavailable at this target).
// features: [4096,2,128] fp32 ; labels: [4096] (int32/int64 auto-detect) ; out: scalar fp32.
//
//   cf[v*B+b] = bf16( features[b,v,:] normalized * 1/sqrt(T) )   (dot == logit)
//   k_main over upper-tri 128x128 tiles: HMMA bf16 GEMM (m16n8k16),
//     epilogue: s[j] += col sums of neg-masked exp (+ mirrored row sums, I<J),
//     positives (i<j) appended to a global list.
//   k_final: total = sum (2l - log(s_j+e^l) - log(s_i+e^l));  out = -total/N

#define BATCH 4096
#define NN    8192
#define BT    128
#define INV_SQRT_T 3.7796447300922722f
#define LCAP  (1 << 20)
#define PCAP  1024

// SMEM tile: 128 rows x 136 bf16 (272 B stride; 17*16B -> ldmatrix conflict-free)
#define TSTRIDE_B 272
// dynamic smem offsets
#define OFF_A    0
#define OFF_B    34816
#define OFF_LABA 69632
#define OFF_LABB 70144
#define OFF_ROW  70656
#define OFF_COL  71168
#define OFF_LP   71680
#define OFF_LV   75776
#define OFF_CNT  79872
#define OFF_BASE 79876
#define SMEM_TOT 79888

__device__ __nv_bfloat16 g_cfb[NN * 128];  // normalized bf16 vectors (2 MB)
__device__ int   g_lab[NN];
__device__ float g_s[NN];
__device__ int   g_is64;
__device__ int   g_cnt;
__device__ unsigned g_lp[LCAP];
__device__ float    g_lv[LCAP];

// ---------------- PTX helpers ----------------------------------------------
__device__ __forceinline__ uint32_t smem_u32(const void* p) {
    uint32_t a;
    asm("{ .reg .u64 t; cvta.to.shared.u64 t, %1; cvt.u32.u64 %0, t; }"
        : "=r"(a) : "l"(p));
    return a;
}
__device__ __forceinline__ void ldsm_x4(uint32_t* r, uint32_t addr) {
    asm volatile("ldmatrix.sync.aligned.m8n8.x4.shared.b16 {%0,%1,%2,%3}, [%4];"
        : "=r"(r[0]), "=r"(r[1]), "=r"(r[2]), "=r"(r[3]) : "r"(addr));
}
__device__ __forceinline__ void mma_bf16(float* c, const uint32_t* a,
                                         uint32_t b0, uint32_t b1) {
    asm volatile(
        "mma.sync.aligned.m16n8k16.row.col.f32.bf16.bf16.f32 "
        "{%0,%1,%2,%3}, {%4,%5,%6,%7}, {%8,%9}, {%0,%1,%2,%3};"
        : "+f"(c[0]), "+f"(c[1]), "+f"(c[2]), "+f"(c[3])
        : "r"(a[0]), "r"(a[1]), "r"(a[2]), "r"(a[3]), "r"(b0), "r"(b1));
}

// ---------------- label dtype detect ----------------------------------------
__global__ void k_detect(const int* __restrict__ lab32) {
    __shared__ int s_any[256];
    int v = 0;
    for (int i = threadIdx.x; i < BATCH / 2; i += 256) v |= lab32[2 * i + 1];
    s_any[threadIdx.x] = v;
    __syncthreads();
    for (int o = 128; o; o >>= 1) {
        if (threadIdx.x < o) s_any[threadIdx.x] |= s_any[threadIdx.x + o];
        __syncthreads();
    }
    if (threadIdx.x == 0) g_is64 = (s_any[0] == 0) ? 1 : 0;
}

// ---------------- prep: normalize -> bf16, labels, zero accumulators --------
__global__ void k_prep(const float* __restrict__ feat,
                       const int* __restrict__ lab32,
                       float* __restrict__ out, int out_size) {
    int t = threadIdx.x, warp = t >> 5, lane = t & 31;
    int n = blockIdx.x * 8 + warp;

    if (blockIdx.x == 0) {
        for (int z = t; z < out_size; z += 256) out[z] = 0.0f;
        if (t == 0) g_cnt = 0;
    }
    if (lane == 0) g_s[n] = 0.0f;

    int v = n >> 12, b = n & (BATCH - 1);
    const float4* f4 = reinterpret_cast<const float4*>(feat) + (size_t)(b * 2 + v) * 32;
    float4 x = f4[lane];
    float ss = x.x * x.x + x.y * x.y + x.z * x.z + x.w * x.w;
#pragma unroll
    for (int o = 16; o; o >>= 1) ss += __shfl_xor_sync(0xffffffffu, ss, o);
    float sc = rsqrtf(ss) * INV_SQRT_T;

    __nv_bfloat162 p0 = __float22bfloat162_rn(make_float2(x.x * sc, x.y * sc));
    __nv_bfloat162 p1 = __float22bfloat162_rn(make_float2(x.z * sc, x.w * sc));
    uint2 w;
    w.x = *reinterpret_cast<unsigned*>(&p0);
    w.y = *reinterpret_cast<unsigned*>(&p1);
    reinterpret_cast<uint2*>(g_cfb)[(size_t)n * 32 + lane] = w;

    if (lane == 0) g_lab[n] = g_is64 ? lab32[2 * b] : lab32[b];
}

// ---------------- main: HMMA bf16 128x128 tile + fused epilogue -------------
// 128 threads / 4 warps in 2x2 grid; warp tile 64x64 (4 m-tiles x 8 n-tiles).
__global__ void __launch_bounds__(128, 2) k_main() {
    const int I = blockIdx.y, J = blockIdx.x;
    if (J < I) return;

    extern __shared__ char sm[];
    const uint32_t sb = smem_u32(sm);

    const int t = threadIdx.x, lane = t & 31, wid = t >> 5;
    const int i0 = I * BT, j0 = J * BT;
    const int notdiag = (I != J);
    const int wm = wid >> 1, wn = wid & 1;       // warp position in 2x2
    const int mrow = wm * 64, ncol = wn * 64;

    if (t == 0) *(int*)(sm + OFF_CNT) = 0;
    if (t < 128) {
        ((int*)(sm + OFF_LABA))[t] = g_lab[i0 + t];
        ((int*)(sm + OFF_LABB))[t] = g_lab[j0 + t];
        ((float*)(sm + OFF_ROW))[t] = 0.0f;
        ((float*)(sm + OFF_COL))[t] = 0.0f;
    }

    // ---- load A/B tiles (bf16 K-major, padded stride) ----
    const uint4* g4 = reinterpret_cast<const uint4*>(g_cfb);   // 16 B = 8 bf16
#pragma unroll
    for (int it = 0; it < 16; ++it) {
        int ch = it * 128 + t;
        int r = ch >> 4, c16 = ch & 15;
        uint4 va = g4[(size_t)(i0 + r) * 16 + c16];
        uint4 vb = g4[(size_t)(j0 + r) * 16 + c16];
        *reinterpret_cast<uint4*>(sm + OFF_A + r * TSTRIDE_B + c16 * 16) = va;
        *reinterpret_cast<uint4*>(sm + OFF_B + r * TSTRIDE_B + c16 * 16) = vb;
    }
    __syncthreads();

    // ---- GEMM: acc[mt][nt][4], rows mrow+mt*16+(lane>>2)(+8),
    //            cols ncol+nt*8+(lane&3)*2(+1) ----
    float acc[4][8][4];
#pragma unroll
    for (int mt = 0; mt < 4; ++mt)
#pragma unroll
        for (int nt = 0; nt < 8; ++nt)
#pragma unroll
            for (int q = 0; q < 4; ++q) acc[mt][nt][q] = 0.0f;

    const int lrow = lane & 15;
    const int khalf = (lane >> 4) * 16;          // byte offset within 32B k-span

#pragma unroll
    for (int ks = 0; ks < 8; ++ks) {
        const int kb = ks * 32;                  // byte offset of this k-chunk
        uint32_t af[4][4], bf[4][4];
#pragma unroll
        for (int mt = 0; mt < 4; ++mt)
            ldsm_x4(af[mt], sb + OFF_A + (mrow + mt * 16 + lrow) * TSTRIDE_B + kb + khalf);
#pragma unroll
        for (int nb = 0; nb < 4; ++nb)
            ldsm_x4(bf[nb], sb + OFF_B + (ncol + nb * 16 + lrow) * TSTRIDE_B + kb + khalf);
#pragma unroll
        for (int mt = 0; mt < 4; ++mt)
#pragma unroll
            for (int nt = 0; nt < 8; ++nt) {
                int nb = nt >> 1, hi = nt & 1;
                mma_bf16(acc[mt][nt], af[mt], bf[nb][hi], bf[nb][hi + 2]);
            }
    }

    // ---- epilogue ----
    const int* labA = (const int*)(sm + OFF_LABA);
    const int* labB = (const int*)(sm + OFF_LABB);
    float* rowsum = (float*)(sm + OFF_ROW);
    float* colsum = (float*)(sm + OFF_COL);
    unsigned* slp = (unsigned*)(sm + OFF_LP);
    float*    slv = (float*)(sm + OFF_LV);

    int li[8], lj[16];
#pragma unroll
    for (int r8 = 0; r8 < 8; ++r8)
        li[r8] = labA[mrow + (r8 >> 1) * 16 + (lane >> 2) + (r8 & 1) * 8];
#pragma unroll
    for (int c = 0; c < 16; ++c)
        lj[c] = labB[ncol + (c >> 1) * 8 + (lane & 3) * 2 + (c & 1)];

    float rowp[8], colp[16];
#pragma unroll
    for (int r8 = 0; r8 < 8; ++r8) rowp[r8] = 0.0f;
#pragma unroll
    for (int c = 0; c < 16; ++c) colp[c] = 0.0f;

#pragma unroll
    for (int mt = 0; mt < 4; ++mt)
#pragma unroll
        for (int nt = 0; nt < 8; ++nt)
#pragma unroll
            for (int q = 0; q < 4; ++q) {
                float lv = acc[mt][nt][q];
                int r8 = mt * 2 + (q >> 1);
                int c16 = nt * 2 + (q & 1);
                if (li[r8] != lj[c16]) {
                    float e = __expf(lv);
                    rowp[r8] += e;
                    colp[c16] += e;
                } else {
                    int rl = mrow + mt * 16 + (lane >> 2) + (q >> 1) * 8;
                    int cl = ncol + nt * 8 + (lane & 3) * 2 + (q & 1);
                    if (notdiag || rl < cl) {
                        unsigned pk = ((unsigned)(i0 + rl) << 13) | (unsigned)(j0 + cl);
                        int idx = atomicAdd((int*)(sm + OFF_CNT), 1);
                        if (idx < PCAP) { slp[idx] = pk; slv[idx] = lv; }
                        else {
                            int gsl = atomicAdd(&g_cnt, 1);
                            if (gsl < LCAP) { g_lp[gsl] = pk; g_lv[gsl] = lv; }
                        }
                    }
                }
            }

    // row sums: reduce over lane&3 quad
#pragma unroll
    for (int r8 = 0; r8 < 8; ++r8) {
        rowp[r8] += __shfl_xor_sync(0xffffffffu, rowp[r8], 1);
        rowp[r8] += __shfl_xor_sync(0xffffffffu, rowp[r8], 2);
    }
    if ((lane & 3) == 0) {
#pragma unroll
        for (int r8 = 0; r8 < 8; ++r8)
            atomicAdd(&rowsum[mrow + (r8 >> 1) * 16 + (lane >> 2) + (r8 & 1) * 8], rowp[r8]);
    }
    // col sums: reduce over lane>>2 groups
#pragma unroll
    for (int c = 0; c < 16; ++c) {
        colp[c] += __shfl_xor_sync(0xffffffffu, colp[c], 4);
        colp[c] += __shfl_xor_sync(0xffffffffu, colp[c], 8);
        colp[c] += __shfl_xor_sync(0xffffffffu, colp[c], 16);
    }
    if (lane < 4) {
#pragma unroll
        for (int c = 0; c < 16; ++c)
            atomicAdd(&colsum[ncol + (c >> 1) * 8 + lane * 2 + (c & 1)], colp[c]);
    }
    __syncthreads();

    if (t < 128) {
        atomicAdd(&g_s[j0 + t], colsum[t]);
        if (notdiag) atomicAdd(&g_s[i0 + t], rowsum[t]);
    }

    // bulk-publish positive list
    int np = *(int*)(sm + OFF_CNT);
    if (np > PCAP) np = PCAP;
    if (t == 0) *(int*)(sm + OFF_BASE) = np ? atomicAdd(&g_cnt, np) : 0;
    __syncthreads();
    int gb = *(int*)(sm + OFF_BASE);
    for (int k = t; k < np; k += 128) {
        int dst = gb + k;
        if (dst < LCAP) { g_lp[dst] = slp[k]; g_lv[dst] = slv[k]; }
    }
}

// ---------------- finalize: loss over the positive list ---------------------
__global__ void k_final(float* __restrict__ out) {
    __shared__ float red[8];
    int cnt = g_cnt; if (cnt > LCAP) cnt = LCAP;
    int idx = blockIdx.x * 256 + threadIdx.x;
    int stride = gridDim.x * 256;
    float local = 0.f;
    for (int k = idx; k < cnt; k += stride) {
        unsigned p = g_lp[k];
        int i = p >> 13, j = p & 8191;
        float l = g_lv[k];
        float e = __expf(l);
        local += 2.0f * l - __logf(g_s[j] + e) - __logf(g_s[i] + e);
    }
#pragma unroll
    for (int o = 16; o; o >>= 1) local += __shfl_xor_sync(0xffffffffu, local, o);
    if ((threadIdx.x & 31) == 0) red[threadIdx.x >> 5] = local;
    __syncthreads();
    if (threadIdx.x == 0) {
        float s = 0.f;
#pragma unroll
        for (int w = 0; w < 8; ++w) s += red[w];
        if (s != 0.0f) atomicAdd(out, s * (-1.0f / (float)NN));
    }
}

// ---------------------------------------------------------------------------
extern "C" void kernel_launch(void* const* d_in, const int* in_sizes, int n_in,
                              void* d_out, int out_size) {
    const float* feat  = (const float*)d_in[0];
    const int*   lab32 = (const int*)d_in[1];
    float*       out   = (float*)d_out;

    cudaFuncSetAttribute(k_main, cudaFuncAttributeMaxDynamicSharedMemorySize,
                         SMEM_TOT);

    k_detect<<<1, 256>>>(lab32);
    k_prep<<<NN / 8, 256>>>(feat, lab32, out, out_size);
    dim3 grid(NN / BT, NN / BT);          // lower-triangle blocks exit
    k_main<<<grid, 128, SMEM_TOT>>>();
    k_final<<<512, 256>>>(out);
}